// round 1
// baseline (speedup 1.0000x reference)
#include <cuda_runtime.h>

#define N_NODES 40000
#define N_EDGES 640000
#define HID 128

// ---------------- scratch (static __device__, no allocations) ----------------
__device__ float g_bufA  [N_NODES * HID];      // 20.5 MB
__device__ float g_bufAgg[N_NODES * HID];      // 20.5 MB
__device__ float g_bufH  [N_NODES * HID];      // 20.5 MB
__device__ float g_bufCat[N_NODES * 2 * HID];  // 41 MB
__device__ int   g_cnt   [N_NODES];
__device__ int   g_rp    [N_NODES + 1];
__device__ int   g_cursor[N_NODES];
__device__ int   g_csrc  [N_EDGES];

// ---------------- f32x2 helpers ----------------
__device__ __forceinline__ unsigned long long fma2(unsigned long long a,
                                                   unsigned long long b,
                                                   unsigned long long c) {
    unsigned long long d;
    asm("fma.rn.f32x2 %0, %1, %2, %3;" : "=l"(d) : "l"(a), "l"(b), "l"(c));
    return d;
}
__device__ __forceinline__ unsigned long long pack2dup(float x) {
    unsigned long long d;
    asm("mov.b64 %0, {%1, %2};" : "=l"(d) : "f"(x), "f"(x));
    return d;
}
__device__ __forceinline__ float2 unpack2(unsigned long long v) {
    float x, y;
    asm("mov.b64 {%0, %1}, %2;" : "=f"(x), "=f"(y) : "l"(v));
    return make_float2(x, y);
}

// ---------------- CSR build (counting sort by dst) ----------------
__global__ void k_zero_cnt() {
    int i = blockIdx.x * blockDim.x + threadIdx.x;
    if (i < N_NODES) g_cnt[i] = 0;
}

__global__ void k_hist(const int* __restrict__ dst) {
    int e = blockIdx.x * blockDim.x + threadIdx.x;
    if (e < N_EDGES) atomicAdd(&g_cnt[dst[e]], 1);
}

__global__ void k_scan() {
    __shared__ int sh[1024];
    const int tid = threadIdx.x;
    int carry = 0;
    for (int base = 0; base < N_NODES; base += 1024) {
        int i = base + tid;
        int v = (i < N_NODES) ? g_cnt[i] : 0;
        sh[tid] = v;
        __syncthreads();
#pragma unroll
        for (int off = 1; off < 1024; off <<= 1) {
            int t = (tid >= off) ? sh[tid - off] : 0;
            __syncthreads();
            sh[tid] += t;
            __syncthreads();
        }
        int excl = carry + sh[tid] - v;
        if (i < N_NODES) { g_rp[i] = excl; g_cursor[i] = excl; }
        carry += sh[1023];
        __syncthreads();
    }
    if (tid == 0) g_rp[N_NODES] = carry;
}

__global__ void k_fill(const int* __restrict__ src, const int* __restrict__ dst) {
    int e = blockIdx.x * blockDim.x + threadIdx.x;
    if (e < N_EDGES) {
        int p = atomicAdd(&g_cursor[dst[e]], 1);
        g_csrc[p] = src[e];
    }
}

// ---------------- embed: relu(x[M,11] @ w[128,11]^T + b) ----------------
__global__ void k_lin_in(const float* __restrict__ x, const float* __restrict__ w,
                         const float* __restrict__ b, float* __restrict__ out) {
    __shared__ float xs[128 * 11];
    const int tid = threadIdx.x;  // 128 threads = output columns
    float wr[11];
#pragma unroll
    for (int k = 0; k < 11; k++) wr[k] = w[tid * 11 + k];
    const float bb = b[tid];
    const int row0 = blockIdx.x * 128;
    const int nr = min(128, N_NODES - row0);
    const int lim = nr * 11;
    for (int idx = tid; idx < 128 * 11; idx += 128)
        xs[idx] = (idx < lim) ? x[row0 * 11 + idx] : 0.f;
    __syncthreads();
    for (int r = 0; r < nr; r++) {
        float acc = bb;
#pragma unroll
        for (int k = 0; k < 11; k++) acc += xs[r * 11 + k] * wr[k];
        out[(size_t)(row0 + r) * HID + tid] = fmaxf(acc, 0.f);
    }
}

// ---------------- SpMM: agg[d] = sum over edges (dst=d) of h[src] ----------------
__global__ void k_spmm(const float* __restrict__ h, int lda, float* __restrict__ agg) {
    const int gw = (blockIdx.x * blockDim.x + threadIdx.x) >> 5;
    const int lane = threadIdx.x & 31;
    if (gw >= N_NODES) return;
    const int beg = g_rp[gw], end = g_rp[gw + 1];
    float4 acc = make_float4(0.f, 0.f, 0.f, 0.f);
    int e = beg;
    for (; e + 1 < end; e += 2) {
        int s0 = g_csrc[e];
        int s1 = g_csrc[e + 1];
        float4 v0 = *(const float4*)(h + (size_t)s0 * lda + (lane << 2));
        float4 v1 = *(const float4*)(h + (size_t)s1 * lda + (lane << 2));
        acc.x += v0.x + v1.x;
        acc.y += v0.y + v1.y;
        acc.z += v0.z + v1.z;
        acc.w += v0.w + v1.w;
    }
    if (e < end) {
        int s0 = g_csrc[e];
        float4 v0 = *(const float4*)(h + (size_t)s0 * lda + (lane << 2));
        acc.x += v0.x; acc.y += v0.y; acc.z += v0.z; acc.w += v0.w;
    }
    *(float4*)(agg + (size_t)gw * HID + (lane << 2)) = acc;
}

// ---------------- GEMM: C[M,128] = act(A[M,K] @ W[128,K]^T + b) ----------------
// BM=160 (40000/160 = 250 blocks exactly), BN=128, BK=8, 256 threads,
// thread tile 10 rows x 8 cols, accumulators packed f32x2 over column pairs.
__global__ __launch_bounds__(256, 1)
void k_gemm(const float* __restrict__ A, int lda,
            const float* __restrict__ W,     // [128, K] row-major (out, in)
            const float* __restrict__ bias,  // [128]
            float* __restrict__ C, int ldc, int K, int doRelu) {
    __shared__ __align__(16) float As[2][8][164];  // padded: bank-conflict-free
    __shared__ __align__(16) float Ws[2][8][128];  // Ws[k][n] = W[n][k0+k]

    const int tid = threadIdx.x;
    const int warp = tid >> 5, lane = tid & 31;
    const int wr = warp >> 1, wc = warp & 1;
    const int tr = lane >> 3, tc = lane & 7;
    const int rowbase = wr * 40 + tr * 10;   // in-tile row of first output
    const int colbase = wc * 64 + tc * 8;    // in-tile col of first output
    const int row0 = blockIdx.x * 160;
    const int kA = tid & 7, rA = tid >> 3;   // A-tile loader coords (5 scalars)
    const int nW = tid >> 1, hW = tid & 1;   // W-tile loader coords (1 float4)

    unsigned long long acc[10][4];
#pragma unroll
    for (int i = 0; i < 10; i++)
#pragma unroll
        for (int c = 0; c < 4; c++) acc[i][c] = 0ull;

    const int nt = K >> 3;
    float pa[5];
    float4 pw;

    // prefetch + store tile 0
#pragma unroll
    for (int j = 0; j < 5; j++)
        pa[j] = A[(size_t)(row0 + rA + 32 * j) * lda + kA];
    pw = *(const float4*)(W + (size_t)nW * K + hW * 4);
#pragma unroll
    for (int j = 0; j < 5; j++) As[0][kA][rA + 32 * j] = pa[j];
    Ws[0][hW * 4 + 0][nW] = pw.x;
    Ws[0][hW * 4 + 1][nW] = pw.y;
    Ws[0][hW * 4 + 2][nW] = pw.z;
    Ws[0][hW * 4 + 3][nW] = pw.w;
    __syncthreads();

    for (int kt = 0; kt < nt; kt++) {
        const int cur = kt & 1;
        if (kt + 1 < nt) {
            const int k0 = (kt + 1) << 3;
#pragma unroll
            for (int j = 0; j < 5; j++)
                pa[j] = A[(size_t)(row0 + rA + 32 * j) * lda + k0 + kA];
            pw = *(const float4*)(W + (size_t)nW * K + k0 + hW * 4);
        }
#pragma unroll
        for (int kk = 0; kk < 8; kk++) {
            unsigned long long av[10], bv[4];
#pragma unroll
            for (int i = 0; i < 10; i++) {
                float a = As[cur][kk][rowbase + i];
                av[i] = pack2dup(a);
            }
#pragma unroll
            for (int c = 0; c < 4; c++)
                bv[c] = *(const unsigned long long*)&Ws[cur][kk][colbase + 2 * c];
#pragma unroll
            for (int i = 0; i < 10; i++)
#pragma unroll
                for (int c = 0; c < 4; c++)
                    acc[i][c] = fma2(av[i], bv[c], acc[i][c]);
        }
        if (kt + 1 < nt) {
            const int nb = (kt + 1) & 1;
#pragma unroll
            for (int j = 0; j < 5; j++) As[nb][kA][rA + 32 * j] = pa[j];
            Ws[nb][hW * 4 + 0][nW] = pw.x;
            Ws[nb][hW * 4 + 1][nW] = pw.y;
            Ws[nb][hW * 4 + 2][nW] = pw.z;
            Ws[nb][hW * 4 + 3][nW] = pw.w;
            __syncthreads();
        }
    }

    float2 bb[4];
#pragma unroll
    for (int c = 0; c < 4; c++)
        bb[c] = *(const float2*)(bias + colbase + 2 * c);
#pragma unroll
    for (int i = 0; i < 10; i++) {
        const int row = row0 + rowbase + i;
#pragma unroll
        for (int c = 0; c < 4; c++) {
            float2 v = unpack2(acc[i][c]);
            v.x += bb[c].x;
            v.y += bb[c].y;
            if (doRelu) { v.x = fmaxf(v.x, 0.f); v.y = fmaxf(v.y, 0.f); }
            *(float2*)(C + (size_t)row * ldc + colbase + 2 * c) = v;
        }
    }
}

// ---------------- head: out[i] = t[i,:] . w[1,128] + b ----------------
__global__ void k_head(const float* __restrict__ t, const float* __restrict__ w,
                       const float* __restrict__ b, float* __restrict__ out) {
    const int gw = (blockIdx.x * blockDim.x + threadIdx.x) >> 5;
    const int lane = threadIdx.x & 31;
    if (gw >= N_NODES) return;
    float4 tv = *(const float4*)(t + (size_t)gw * HID + (lane << 2));
    float4 wv = *(const float4*)(w + (lane << 2));
    float s = tv.x * wv.x + tv.y * wv.y + tv.z * wv.z + tv.w * wv.w;
#pragma unroll
    for (int off = 16; off; off >>= 1) s += __shfl_xor_sync(0xffffffffu, s, off);
    if (lane == 0) out[gw] = s + b[0];
}

// ---------------- launch ----------------
extern "C" void kernel_launch(void* const* d_in, const int* in_sizes, int n_in,
                              void* d_out, int out_size) {
    const float* x     = (const float*)d_in[0];
    const int*   ei    = (const int*)d_in[1];
    const float* c0_w1 = (const float*)d_in[2];
    const float* c0_b1 = (const float*)d_in[3];
    const float* c0_w2 = (const float*)d_in[4];
    const float* c0_b2 = (const float*)d_in[5];
    const float* c0_w3 = (const float*)d_in[6];
    const float* c0_b3 = (const float*)d_in[7];
    const float* c1_w1 = (const float*)d_in[8];
    const float* c1_b1 = (const float*)d_in[9];
    const float* c1_w2 = (const float*)d_in[10];
    const float* c1_b2 = (const float*)d_in[11];
    const float* c1_w3 = (const float*)d_in[12];
    const float* c1_b3 = (const float*)d_in[13];
    const float* f_w1  = (const float*)d_in[14];
    const float* f_b1  = (const float*)d_in[15];
    const float* f_w2  = (const float*)d_in[16];
    const float* f_b2  = (const float*)d_in[17];
    float* out = (float*)d_out;

    const int* src = ei;
    const int* dst = ei + N_EDGES;

    float *bufA, *bufAgg, *bufH, *bufCat;
    cudaGetSymbolAddress((void**)&bufA,   g_bufA);
    cudaGetSymbolAddress((void**)&bufAgg, g_bufAgg);
    cudaGetSymbolAddress((void**)&bufH,   g_bufH);
    cudaGetSymbolAddress((void**)&bufCat, g_bufCat);

    const int TB = 256;
    const dim3 gEdges((N_EDGES + TB - 1) / TB);
    const dim3 gNodes((N_NODES + TB - 1) / TB);
    const dim3 gWarpPerNode((N_NODES * 32 + TB - 1) / TB);  // 5000
    const dim3 gGemm(N_NODES / 160);                         // 250, exact
    const dim3 gLinIn((N_NODES + 127) / 128);                // 313

    // CSR build (by dst)
    k_zero_cnt<<<gNodes, TB>>>();
    k_hist<<<gEdges, TB>>>(dst);
    k_scan<<<1, 1024>>>();
    k_fill<<<gEdges, TB>>>(src, dst);

    // conv0
    k_lin_in<<<gLinIn, 128>>>(x, c0_w1, c0_b1, bufA);                          // h = relu(lin1(x))
    k_spmm<<<gWarpPerNode, TB>>>(bufA, HID, bufAgg);                           // agg = A h
    k_gemm<<<gGemm, TB>>>(bufAgg, HID, c0_w2, c0_b2, bufCat, 2 * HID, HID, 1); // lvl0 -> cat[:, :128]
    k_spmm<<<gWarpPerNode, TB>>>(bufCat, 2 * HID, bufAgg);                     // agg = A lvl0
    k_gemm<<<gGemm, TB>>>(bufAgg, HID, c0_w2, c0_b2, bufCat + HID, 2 * HID, HID, 1); // lvl1 -> cat[:, 128:]
    k_gemm<<<gGemm, TB>>>(bufCat, 2 * HID, c0_w3, c0_b3, bufH, HID, 2 * HID, 0);     // h = lin3(cat)

    // conv1
    k_gemm<<<gGemm, TB>>>(bufH, HID, c1_w1, c1_b1, bufA, HID, HID, 1);
    k_spmm<<<gWarpPerNode, TB>>>(bufA, HID, bufAgg);
    k_gemm<<<gGemm, TB>>>(bufAgg, HID, c1_w2, c1_b2, bufCat, 2 * HID, HID, 1);
    k_spmm<<<gWarpPerNode, TB>>>(bufCat, 2 * HID, bufAgg);
    k_gemm<<<gGemm, TB>>>(bufAgg, HID, c1_w2, c1_b2, bufCat + HID, 2 * HID, HID, 1);
    k_gemm<<<gGemm, TB>>>(bufCat, 2 * HID, c1_w3, c1_b3, bufH, HID, 2 * HID, 0);

    // head
    k_gemm<<<gGemm, TB>>>(bufH, HID, f_w1, f_b1, bufA, HID, HID, 1);
    k_head<<<gWarpPerNode, TB>>>(bufA, f_w2, f_b2, out);
}

// round 2
// speedup vs baseline: 1.0533x; 1.0533x over previous
#include <cuda_runtime.h>

#define N_NODES 40000
#define N_EDGES 640000
#define HID 128

// ---------------- scratch (static __device__, no allocations) ----------------
__device__ float g_bufA  [N_NODES * HID];
__device__ float g_bufAgg[N_NODES * HID];
__device__ float g_bufH  [N_NODES * HID];
__device__ float g_bufCat[N_NODES * 2 * HID];
__device__ int   g_cnt   [N_NODES];
__device__ int   g_rp    [N_NODES + 1];
__device__ int   g_cursor[N_NODES];
__device__ int   g_csrc  [N_EDGES];

// ---------------- f32x2 helpers ----------------
__device__ __forceinline__ unsigned long long fma2(unsigned long long a,
                                                   unsigned long long b,
                                                   unsigned long long c) {
    unsigned long long d;
    asm("fma.rn.f32x2 %0, %1, %2, %3;" : "=l"(d) : "l"(a), "l"(b), "l"(c));
    return d;
}
__device__ __forceinline__ unsigned long long pack2dup(float x) {
    unsigned long long d;
    asm("mov.b64 %0, {%1, %2};" : "=l"(d) : "f"(x), "f"(x));
    return d;
}
__device__ __forceinline__ float2 unpack2(unsigned long long v) {
    float x, y;
    asm("mov.b64 {%0, %1}, %2;" : "=f"(x), "=f"(y) : "l"(v));
    return make_float2(x, y);
}

// ---------------- CSR build (counting sort by dst) ----------------
__global__ void k_hist(const int* __restrict__ dst) {
    int e = blockIdx.x * blockDim.x + threadIdx.x;
    if (e < N_EDGES) atomicAdd(&g_cnt[dst[e]], 1);
}

// warp-shuffle scan: 3 syncthreads per 1024-chunk instead of 20
__global__ void k_scan() {
    __shared__ int warpsum[32];
    __shared__ int sh_carry;
    const int tid = threadIdx.x;
    const int lane = tid & 31, wid = tid >> 5;
    if (tid == 0) sh_carry = 0;
    __syncthreads();
    for (int base = 0; base < N_NODES; base += 1024) {
        int i = base + tid;
        int v = (i < N_NODES) ? g_cnt[i] : 0;
        int s = v;
#pragma unroll
        for (int o = 1; o < 32; o <<= 1) {
            int t = __shfl_up_sync(0xffffffffu, s, o);
            if (lane >= o) s += t;
        }
        if (lane == 31) warpsum[wid] = s;
        __syncthreads();
        if (wid == 0) {
            int w = warpsum[lane];
#pragma unroll
            for (int o = 1; o < 32; o <<= 1) {
                int t = __shfl_up_sync(0xffffffffu, w, o);
                if (lane >= o) w += t;
            }
            warpsum[lane] = w;
        }
        __syncthreads();
        int incl = s + (wid ? warpsum[wid - 1] : 0) + sh_carry;
        int excl = incl - v;
        if (i < N_NODES) { g_rp[i] = excl; g_cursor[i] = excl; }
        __syncthreads();  // protect warpsum + sh_carry reuse
        if (tid == 1023) sh_carry = incl;
        __syncthreads();
    }
    if (tid == 0) g_rp[N_NODES] = sh_carry;
}

__global__ void k_fill(const int* __restrict__ src, const int* __restrict__ dst) {
    int e = blockIdx.x * blockDim.x + threadIdx.x;
    if (e < N_EDGES) {
        int p = atomicAdd(&g_cursor[dst[e]], 1);
        g_csrc[p] = src[e];
    }
}

// ---------------- embed: relu(x[M,11] @ w[128,11]^T + b) ----------------
__global__ void k_lin_in(const float* __restrict__ x, const float* __restrict__ w,
                         const float* __restrict__ b, float* __restrict__ out) {
    __shared__ float xs[128 * 11];
    const int tid = threadIdx.x;  // 128 threads = output columns
    float wr[11];
#pragma unroll
    for (int k = 0; k < 11; k++) wr[k] = w[tid * 11 + k];
    const float bb = b[tid];
    const int row0 = blockIdx.x * 128;
    const int nr = min(128, N_NODES - row0);
    const int lim = nr * 11;
    for (int idx = tid; idx < 128 * 11; idx += 128)
        xs[idx] = (idx < lim) ? x[row0 * 11 + idx] : 0.f;
    __syncthreads();
    for (int r = 0; r < nr; r++) {
        float acc = bb;
#pragma unroll
        for (int k = 0; k < 11; k++) acc += xs[r * 11 + k] * wr[k];
        out[(size_t)(row0 + r) * HID + tid] = fmaxf(acc, 0.f);
    }
}

// ---------------- SpMM: agg[d] = sum over edges (dst=d) of h[src] ----------------
__global__ void k_spmm(const float* __restrict__ h, int lda, float* __restrict__ agg) {
    const int gw = (blockIdx.x * blockDim.x + threadIdx.x) >> 5;
    const int lane = threadIdx.x & 31;
    if (gw >= N_NODES) return;
    const int beg = g_rp[gw], end = g_rp[gw + 1];
    const int off = lane << 2;
    float4 acc = make_float4(0.f, 0.f, 0.f, 0.f);
    int e = beg;
    for (; e + 3 < end; e += 4) {
        int s0 = g_csrc[e], s1 = g_csrc[e + 1], s2 = g_csrc[e + 2], s3 = g_csrc[e + 3];
        float4 v0 = *(const float4*)(h + (size_t)s0 * lda + off);
        float4 v1 = *(const float4*)(h + (size_t)s1 * lda + off);
        float4 v2 = *(const float4*)(h + (size_t)s2 * lda + off);
        float4 v3 = *(const float4*)(h + (size_t)s3 * lda + off);
        acc.x += (v0.x + v1.x) + (v2.x + v3.x);
        acc.y += (v0.y + v1.y) + (v2.y + v3.y);
        acc.z += (v0.z + v1.z) + (v2.z + v3.z);
        acc.w += (v0.w + v1.w) + (v2.w + v3.w);
    }
    for (; e < end; e++) {
        int s0 = g_csrc[e];
        float4 v0 = *(const float4*)(h + (size_t)s0 * lda + off);
        acc.x += v0.x; acc.y += v0.y; acc.z += v0.z; acc.w += v0.w;
    }
    *(float4*)(agg + (size_t)gw * HID + off) = acc;
}

// ---------------- GEMM: C[M,128] = act(A[M,K] @ W[128,K]^T + b) ----------------
// BM=160 (250 blocks), BN=128, BK=8, 256 threads, occ=2 per SM.
// Thread tile 10 rows x 8 cols, f32x2-packed accumulators over column pairs.
__global__ __launch_bounds__(256, 2)
void k_gemm(const float* __restrict__ A, int lda,
            const float* __restrict__ W,     // [128, K] row-major (out, in)
            const float* __restrict__ bias,  // [128]
            float* __restrict__ C, int ldc, int K, int doRelu) {
    __shared__ __align__(16) float As[2][8][164];
    __shared__ __align__(16) float Ws[2][8][128];

    const int tid = threadIdx.x;
    const int warp = tid >> 5, lane = tid & 31;
    const int wr = warp >> 1, wc = warp & 1;
    const int tr = lane >> 3, tc = lane & 7;
    const int rowbase = wr * 40 + tr * 10;
    const int colbase = wc * 64 + tc * 8;
    const int row0 = blockIdx.x * 160;
    const int kA = tid & 7, rA = tid >> 3;
    const int nW = tid >> 1, hW = tid & 1;

    unsigned long long acc[10][4];
#pragma unroll
    for (int i = 0; i < 10; i++)
#pragma unroll
        for (int c = 0; c < 4; c++) acc[i][c] = 0ull;

    const int nt = K >> 3;
    float pa[5];
    float4 pw;

#pragma unroll
    for (int j = 0; j < 5; j++)
        pa[j] = A[(size_t)(row0 + rA + 32 * j) * lda + kA];
    pw = *(const float4*)(W + (size_t)nW * K + hW * 4);
#pragma unroll
    for (int j = 0; j < 5; j++) As[0][kA][rA + 32 * j] = pa[j];
    Ws[0][hW * 4 + 0][nW] = pw.x;
    Ws[0][hW * 4 + 1][nW] = pw.y;
    Ws[0][hW * 4 + 2][nW] = pw.z;
    Ws[0][hW * 4 + 3][nW] = pw.w;
    __syncthreads();

    for (int kt = 0; kt < nt; kt++) {
        const int cur = kt & 1;
        if (kt + 1 < nt) {
            const int k0 = (kt + 1) << 3;
#pragma unroll
            for (int j = 0; j < 5; j++)
                pa[j] = A[(size_t)(row0 + rA + 32 * j) * lda + k0 + kA];
            pw = *(const float4*)(W + (size_t)nW * K + k0 + hW * 4);
        }
#pragma unroll
        for (int kk = 0; kk < 8; kk++) {
            unsigned long long bv[4];
#pragma unroll
            for (int c = 0; c < 4; c++)
                bv[c] = *(const unsigned long long*)&Ws[cur][kk][colbase + 2 * c];
#pragma unroll
            for (int i = 0; i < 10; i++) {
                unsigned long long av = pack2dup(As[cur][kk][rowbase + i]);
#pragma unroll
                for (int c = 0; c < 4; c++)
                    acc[i][c] = fma2(av, bv[c], acc[i][c]);
            }
        }
        if (kt + 1 < nt) {
            const int nb = (kt + 1) & 1;
#pragma unroll
            for (int j = 0; j < 5; j++) As[nb][kA][rA + 32 * j] = pa[j];
            Ws[nb][hW * 4 + 0][nW] = pw.x;
            Ws[nb][hW * 4 + 1][nW] = pw.y;
            Ws[nb][hW * 4 + 2][nW] = pw.z;
            Ws[nb][hW * 4 + 3][nW] = pw.w;
            __syncthreads();
        }
    }

    float2 bb[4];
#pragma unroll
    for (int c = 0; c < 4; c++)
        bb[c] = *(const float2*)(bias + colbase + 2 * c);
#pragma unroll
    for (int i = 0; i < 10; i++) {
        const int row = row0 + rowbase + i;
#pragma unroll
        for (int c = 0; c < 4; c++) {
            float2 v = unpack2(acc[i][c]);
            v.x += bb[c].x;
            v.y += bb[c].y;
            if (doRelu) { v.x = fmaxf(v.x, 0.f); v.y = fmaxf(v.y, 0.f); }
            *(float2*)(C + (size_t)row * ldc + colbase + 2 * c) = v;
        }
    }
}

// ---------------- head: out[i] = t[i,:] . w[1,128] + b ----------------
__global__ void k_head(const float* __restrict__ t, const float* __restrict__ w,
                       const float* __restrict__ b, float* __restrict__ out) {
    const int gw = (blockIdx.x * blockDim.x + threadIdx.x) >> 5;
    const int lane = threadIdx.x & 31;
    if (gw >= N_NODES) return;
    float4 tv = *(const float4*)(t + (size_t)gw * HID + (lane << 2));
    float4 wv = *(const float4*)(w + (lane << 2));
    float s = tv.x * wv.x + tv.y * wv.y + tv.z * wv.z + tv.w * wv.w;
#pragma unroll
    for (int off = 16; off; off >>= 1) s += __shfl_xor_sync(0xffffffffu, s, off);
    if (lane == 0) out[gw] = s + b[0];
}

// ---------------- launch ----------------
extern "C" void kernel_launch(void* const* d_in, const int* in_sizes, int n_in,
                              void* d_out, int out_size) {
    const float* x     = (const float*)d_in[0];
    const int*   ei    = (const int*)d_in[1];
    const float* c0_w1 = (const float*)d_in[2];
    const float* c0_b1 = (const float*)d_in[3];
    const float* c0_w2 = (const float*)d_in[4];
    const float* c0_b2 = (const float*)d_in[5];
    const float* c0_w3 = (const float*)d_in[6];
    const float* c0_b3 = (const float*)d_in[7];
    const float* c1_w1 = (const float*)d_in[8];
    const float* c1_b1 = (const float*)d_in[9];
    const float* c1_w2 = (const float*)d_in[10];
    const float* c1_b2 = (const float*)d_in[11];
    const float* c1_w3 = (const float*)d_in[12];
    const float* c1_b3 = (const float*)d_in[13];
    const float* f_w1  = (const float*)d_in[14];
    const float* f_b1  = (const float*)d_in[15];
    const float* f_w2  = (const float*)d_in[16];
    const float* f_b2  = (const float*)d_in[17];
    float* out = (float*)d_out;

    const int* src = ei;
    const int* dst = ei + N_EDGES;

    float *bufA, *bufAgg, *bufH, *bufCat;
    int* cntp;
    cudaGetSymbolAddress((void**)&bufA,   g_bufA);
    cudaGetSymbolAddress((void**)&bufAgg, g_bufAgg);
    cudaGetSymbolAddress((void**)&bufH,   g_bufH);
    cudaGetSymbolAddress((void**)&bufCat, g_bufCat);
    cudaGetSymbolAddress((void**)&cntp,   g_cnt);

    const int TB = 256;
    const dim3 gEdges((N_EDGES + TB - 1) / TB);
    const dim3 gWarpPerNode((N_NODES * 32 + TB - 1) / TB);  // 5000
    const dim3 gGemm(N_NODES / 160);                         // 250
    const dim3 gLinIn((N_NODES + 127) / 128);                // 313

    // CSR build (by dst)
    cudaMemsetAsync(cntp, 0, N_NODES * sizeof(int), 0);
    k_hist<<<gEdges, TB>>>(dst);
    k_scan<<<1, 1024>>>();
    k_fill<<<gEdges, TB>>>(src, dst);

    // conv0
    k_lin_in<<<gLinIn, 128>>>(x, c0_w1, c0_b1, bufA);
    k_spmm<<<gWarpPerNode, TB>>>(bufA, HID, bufAgg);
    k_gemm<<<gGemm, TB>>>(bufAgg, HID, c0_w2, c0_b2, bufCat, 2 * HID, HID, 1);
    k_spmm<<<gWarpPerNode, TB>>>(bufCat, 2 * HID, bufAgg);
    k_gemm<<<gGemm, TB>>>(bufAgg, HID, c0_w2, c0_b2, bufCat + HID, 2 * HID, HID, 1);
    k_gemm<<<gGemm, TB>>>(bufCat, 2 * HID, c0_w3, c0_b3, bufH, HID, 2 * HID, 0);

    // conv1
    k_gemm<<<gGemm, TB>>>(bufH, HID, c1_w1, c1_b1, bufA, HID, HID, 1);
    k_spmm<<<gWarpPerNode, TB>>>(bufA, HID, bufAgg);
    k_gemm<<<gGemm, TB>>>(bufAgg, HID, c1_w2, c1_b2, bufCat, 2 * HID, HID, 1);
    k_spmm<<<gWarpPerNode, TB>>>(bufCat, 2 * HID, bufAgg);
    k_gemm<<<gGemm, TB>>>(bufAgg, HID, c1_w2, c1_b2, bufCat + HID, 2 * HID, HID, 1);
    k_gemm<<<gGemm, TB>>>(bufCat, 2 * HID, c1_w3, c1_b3, bufH, HID, 2 * HID, 0);

    // head
    k_gemm<<<gGemm, TB>>>(bufH, HID, f_w1, f_b1, bufA, HID, HID, 1);
    k_head<<<gWarpPerNode, TB>>>(bufA, f_w2, f_b2, out);
}

// round 4
// speedup vs baseline: 1.6294x; 1.5469x over previous
#include <cuda_runtime.h>
#include <cuda_bf16.h>
#include <cstdint>

#define N_NODES 40000
#define N_EDGES 640000
#define HID 128

// ---------------- scratch (static __device__, no allocations) ----------------
__device__ float g_bufA  [N_NODES * HID];
__device__ float g_bufAgg[N_NODES * HID];
__device__ float g_bufH  [N_NODES * HID];
__device__ float g_bufCat[N_NODES * 2 * HID];
__device__ int   g_cnt   [N_NODES];
__device__ int   g_rp    [N_NODES + 1];
__device__ int   g_cursor[N_NODES];
__device__ int   g_csrc  [N_EDGES];

// ---------------- CSR build (counting sort by dst) ----------------
__global__ void k_hist(const int* __restrict__ dst) {
    int e = blockIdx.x * blockDim.x + threadIdx.x;
    if (e < N_EDGES) atomicAdd(&g_cnt[dst[e]], 1);
}

__global__ void k_scan() {
    __shared__ int warpsum[32];
    __shared__ int sh_carry;
    const int tid = threadIdx.x;
    const int lane = tid & 31, wid = tid >> 5;
    if (tid == 0) sh_carry = 0;
    __syncthreads();
    for (int base = 0; base < N_NODES; base += 1024) {
        int i = base + tid;
        int v = (i < N_NODES) ? g_cnt[i] : 0;
        int s = v;
#pragma unroll
        for (int o = 1; o < 32; o <<= 1) {
            int t = __shfl_up_sync(0xffffffffu, s, o);
            if (lane >= o) s += t;
        }
        if (lane == 31) warpsum[wid] = s;
        __syncthreads();
        if (wid == 0) {
            int w = warpsum[lane];
#pragma unroll
            for (int o = 1; o < 32; o <<= 1) {
                int t = __shfl_up_sync(0xffffffffu, w, o);
                if (lane >= o) w += t;
            }
            warpsum[lane] = w;
        }
        __syncthreads();
        int incl = s + (wid ? warpsum[wid - 1] : 0) + sh_carry;
        int excl = incl - v;
        if (i < N_NODES) { g_rp[i] = excl; g_cursor[i] = excl; }
        __syncthreads();
        if (tid == 1023) sh_carry = incl;
        __syncthreads();
    }
    if (tid == 0) g_rp[N_NODES] = sh_carry;
}

__global__ void k_fill(const int* __restrict__ src, const int* __restrict__ dst) {
    int e = blockIdx.x * blockDim.x + threadIdx.x;
    if (e < N_EDGES) {
        int p = atomicAdd(&g_cursor[dst[e]], 1);
        g_csrc[p] = src[e];
    }
}

// ---------------- embed: relu(x[M,11] @ w[128,11]^T + b) ----------------
__global__ void k_lin_in(const float* __restrict__ x, const float* __restrict__ w,
                         const float* __restrict__ b, float* __restrict__ out) {
    __shared__ float xs[128 * 11];
    const int tid = threadIdx.x;
    float wr[11];
#pragma unroll
    for (int k = 0; k < 11; k++) wr[k] = w[tid * 11 + k];
    const float bb = b[tid];
    const int row0 = blockIdx.x * 128;
    const int nr = min(128, N_NODES - row0);
    const int lim = nr * 11;
    for (int idx = tid; idx < 128 * 11; idx += 128)
        xs[idx] = (idx < lim) ? x[row0 * 11 + idx] : 0.f;
    __syncthreads();
    for (int r = 0; r < nr; r++) {
        float acc = bb;
#pragma unroll
        for (int k = 0; k < 11; k++) acc += xs[r * 11 + k] * wr[k];
        out[(size_t)(row0 + r) * HID + tid] = fmaxf(acc, 0.f);
    }
}

// ---------------- SpMM: agg[d] = sum over edges (dst=d) of h[src] ----------------
__global__ void k_spmm(const float* __restrict__ h, int lda, float* __restrict__ agg) {
    const int gw = (blockIdx.x * blockDim.x + threadIdx.x) >> 5;
    const int lane = threadIdx.x & 31;
    if (gw >= N_NODES) return;
    const int beg = g_rp[gw], end = g_rp[gw + 1];
    const int off = lane << 2;
    float4 acc = make_float4(0.f, 0.f, 0.f, 0.f);
    int e = beg;
    for (; e + 3 < end; e += 4) {
        int s0 = g_csrc[e], s1 = g_csrc[e + 1], s2 = g_csrc[e + 2], s3 = g_csrc[e + 3];
        float4 v0 = *(const float4*)(h + (size_t)s0 * lda + off);
        float4 v1 = *(const float4*)(h + (size_t)s1 * lda + off);
        float4 v2 = *(const float4*)(h + (size_t)s2 * lda + off);
        float4 v3 = *(const float4*)(h + (size_t)s3 * lda + off);
        acc.x += (v0.x + v1.x) + (v2.x + v3.x);
        acc.y += (v0.y + v1.y) + (v2.y + v3.y);
        acc.z += (v0.z + v1.z) + (v2.z + v3.z);
        acc.w += (v0.w + v1.w) + (v2.w + v3.w);
    }
    for (; e < end; e++) {
        int s0 = g_csrc[e];
        float4 v0 = *(const float4*)(h + (size_t)s0 * lda + off);
        acc.x += v0.x; acc.y += v0.y; acc.z += v0.z; acc.w += v0.w;
    }
    *(float4*)(agg + (size_t)gw * HID + off) = acc;
}

// ================= mma.sync bf16x3 GEMM =================
// C[M,128] = act(A[M,K] @ W[128,K]^T + b)
// Block 64x128, 8 warps (2x4), warp tile 32x32, k-step 16.
// fp32 -> bf16 hi/lo split; D = Ah*Wh + Ah*Wl + Al*Wh.

__device__ __forceinline__ uint32_t smem_u32(const void* p) {
    uint32_t a;
    asm("{ .reg .u64 t; cvta.to.shared.u64 t, %1; cvt.u32.u64 %0, t; }"
        : "=r"(a) : "l"(p));
    return a;
}

__device__ __forceinline__ void mma_bf16(float d[4], const uint32_t a[4],
                                         const uint32_t b[2]) {
    asm volatile(
        "mma.sync.aligned.m16n8k16.row.col.f32.bf16.bf16.f32 "
        "{%0,%1,%2,%3}, {%4,%5,%6,%7}, {%8,%9}, {%0,%1,%2,%3};"
        : "+f"(d[0]), "+f"(d[1]), "+f"(d[2]), "+f"(d[3])
        : "r"(a[0]), "r"(a[1]), "r"(a[2]), "r"(a[3]), "r"(b[0]), "r"(b[1]));
}

#define LDMX4(r, addr) \
    asm volatile("ldmatrix.sync.aligned.m8n8.x4.shared.b16 {%0,%1,%2,%3}, [%4];" \
                 : "=r"((r)[0]), "=r"((r)[1]), "=r"((r)[2]), "=r"((r)[3]) : "r"(addr))
#define LDMX2(r, addr) \
    asm volatile("ldmatrix.sync.aligned.m8n8.x2.shared.b16 {%0,%1}, [%2];" \
                 : "=r"((r)[0]), "=r"((r)[1]) : "r"(addr))

__device__ __forceinline__ uint32_t pack_hi(float x, float y, float& lx, float& ly) {
    __nv_bfloat162 h = __floats2bfloat162_rn(x, y);
    lx = x - __bfloat162float(h.x);
    ly = y - __bfloat162float(h.y);
    return *(uint32_t*)&h;
}
__device__ __forceinline__ uint32_t pack_bf2(float x, float y) {
    __nv_bfloat162 h = __floats2bfloat162_rn(x, y);
    return *(uint32_t*)&h;
}

// SMEM per stage: Ahi[64 rows x 48B] =3072, Alo 3072, Whi[128 x 48B] =6144, Wlo 6144
#define ST_AHI 0
#define ST_ALO 3072
#define ST_WHI 6144
#define ST_WLO 12288
#define ST_SZ  18432

__global__ __launch_bounds__(256, 2)
void k_gemm_mma(const float* __restrict__ A, int lda,
                const float* __restrict__ W,     // [128, K] row-major
                const float* __restrict__ bias,  // [128]
                float* __restrict__ C, int ldc, int K, int doRelu) {
    __shared__ __align__(16) char sm[2][ST_SZ];

    const int tid = threadIdx.x, warp = tid >> 5, lane = tid & 31;
    const int wr = warp >> 2, wc = warp & 3;  // 2 x 4 warp grid
    const int row0 = blockIdx.x * 64;

    // loader coords
    const int ar = tid >> 2, aq = tid & 3;  // A: 64 rows x 4 float4
    const int wn = tid >> 1, wh = tid & 1;  // W: 128 rows x 2 halves(8 fp32)

    const float* aptr = A + (size_t)(row0 + ar) * lda + 4 * aq;
    const float* wptr = W + (size_t)wn * K + 8 * wh;

    const uint32_t sA0 = smem_u32(&sm[0][0]);
    const uint32_t sA1 = smem_u32(&sm[1][0]);

    // ldmatrix lane offsets
    const uint32_t a_lo = (uint32_t)(((wr * 32) + (lane & 7) + ((lane >> 3) & 1) * 8) * 48
                                     + ((lane >> 4) * 16));
    const uint32_t b_lo = (uint32_t)(((wc * 32) + (lane & 7)) * 48 + ((lane >> 3) & 1) * 16);

    // store offsets (bytes)
    const uint32_t a_st = (uint32_t)(ar * 48 + 8 * aq);
    const uint32_t w_st = (uint32_t)(wn * 48 + 16 * wh);

    float d[2][4][4];
#pragma unroll
    for (int mt = 0; mt < 2; mt++)
#pragma unroll
        for (int nt = 0; nt < 4; nt++)
#pragma unroll
            for (int i = 0; i < 4; i++) d[mt][nt][i] = 0.f;

    const int nst = K >> 4;
    float4 a4, w4a, w4b;

    // prefetch step 0
    a4 = *(const float4*)aptr;
    w4a = *(const float4*)wptr;
    w4b = *(const float4*)(wptr + 4);

    // store stage 0
    {
        char* st = sm[0];
        float lx, ly;
        uint32_t h01 = pack_hi(a4.x, a4.y, lx, ly);
        uint32_t l01 = pack_bf2(lx, ly);
        uint32_t h23 = pack_hi(a4.z, a4.w, lx, ly);
        uint32_t l23 = pack_bf2(lx, ly);
        *(uint32_t*)(st + ST_AHI + a_st) = h01;
        *(uint32_t*)(st + ST_AHI + a_st + 4) = h23;
        *(uint32_t*)(st + ST_ALO + a_st) = l01;
        *(uint32_t*)(st + ST_ALO + a_st + 4) = l23;
        uint32_t wh01 = pack_hi(w4a.x, w4a.y, lx, ly);
        uint32_t wl01 = pack_bf2(lx, ly);
        uint32_t wh23 = pack_hi(w4a.z, w4a.w, lx, ly);
        uint32_t wl23 = pack_bf2(lx, ly);
        uint32_t wh45 = pack_hi(w4b.x, w4b.y, lx, ly);
        uint32_t wl45 = pack_bf2(lx, ly);
        uint32_t wh67 = pack_hi(w4b.z, w4b.w, lx, ly);
        uint32_t wl67 = pack_bf2(lx, ly);
        *(uint32_t*)(st + ST_WHI + w_st) = wh01;
        *(uint32_t*)(st + ST_WHI + w_st + 4) = wh23;
        *(uint32_t*)(st + ST_WHI + w_st + 8) = wh45;
        *(uint32_t*)(st + ST_WHI + w_st + 12) = wh67;
        *(uint32_t*)(st + ST_WLO + w_st) = wl01;
        *(uint32_t*)(st + ST_WLO + w_st + 4) = wl23;
        *(uint32_t*)(st + ST_WLO + w_st + 8) = wl45;
        *(uint32_t*)(st + ST_WLO + w_st + 12) = wl67;
    }
    __syncthreads();

    for (int s = 0; s < nst; s++) {
        if (s + 1 < nst) {
            a4 = *(const float4*)(aptr + (s + 1) * 16);
            w4a = *(const float4*)(wptr + (s + 1) * 16);
            w4b = *(const float4*)(wptr + (s + 1) * 16 + 4);
        }
        const uint32_t sb = (s & 1) ? sA1 : sA0;

        uint32_t ah[2][4], al[2][4], bh[4][2], bl[4][2];
#pragma unroll
        for (int mt = 0; mt < 2; mt++) {
            LDMX4(ah[mt], sb + ST_AHI + a_lo + mt * 16 * 48);
            LDMX4(al[mt], sb + ST_ALO + a_lo + mt * 16 * 48);
        }
#pragma unroll
        for (int nt = 0; nt < 4; nt++) {
            LDMX2(bh[nt], sb + ST_WHI + b_lo + nt * 8 * 48);
            LDMX2(bl[nt], sb + ST_WLO + b_lo + nt * 8 * 48);
        }
#pragma unroll
        for (int mt = 0; mt < 2; mt++)
#pragma unroll
            for (int nt = 0; nt < 4; nt++) {
                mma_bf16(d[mt][nt], al[mt], bh[nt]);
                mma_bf16(d[mt][nt], ah[mt], bl[nt]);
                mma_bf16(d[mt][nt], ah[mt], bh[nt]);
            }

        if (s + 1 < nst) {
            char* st = sm[(s + 1) & 1];
            float lx, ly;
            uint32_t h01 = pack_hi(a4.x, a4.y, lx, ly);
            uint32_t l01 = pack_bf2(lx, ly);
            uint32_t h23 = pack_hi(a4.z, a4.w, lx, ly);
            uint32_t l23 = pack_bf2(lx, ly);
            *(uint32_t*)(st + ST_AHI + a_st) = h01;
            *(uint32_t*)(st + ST_AHI + a_st + 4) = h23;
            *(uint32_t*)(st + ST_ALO + a_st) = l01;
            *(uint32_t*)(st + ST_ALO + a_st + 4) = l23;
            uint32_t wh01 = pack_hi(w4a.x, w4a.y, lx, ly);
            uint32_t wl01 = pack_bf2(lx, ly);
            uint32_t wh23 = pack_hi(w4a.z, w4a.w, lx, ly);
            uint32_t wl23 = pack_bf2(lx, ly);
            uint32_t wh45 = pack_hi(w4b.x, w4b.y, lx, ly);
            uint32_t wl45 = pack_bf2(lx, ly);
            uint32_t wh67 = pack_hi(w4b.z, w4b.w, lx, ly);
            uint32_t wl67 = pack_bf2(lx, ly);
            *(uint32_t*)(st + ST_WHI + w_st) = wh01;
            *(uint32_t*)(st + ST_WHI + w_st + 4) = wh23;
            *(uint32_t*)(st + ST_WHI + w_st + 8) = wh45;
            *(uint32_t*)(st + ST_WHI + w_st + 12) = wh67;
            *(uint32_t*)(st + ST_WLO + w_st) = wl01;
            *(uint32_t*)(st + ST_WLO + w_st + 4) = wl23;
            *(uint32_t*)(st + ST_WLO + w_st + 8) = wl45;
            *(uint32_t*)(st + ST_WLO + w_st + 12) = wl67;
            __syncthreads();
        }
    }

    // epilogue
#pragma unroll
    for (int mt = 0; mt < 2; mt++) {
        const int row = row0 + wr * 32 + mt * 16 + (lane >> 2);
#pragma unroll
        for (int nt = 0; nt < 4; nt++) {
            const int col = wc * 32 + nt * 8 + 2 * (lane & 3);
            float2 bb = *(const float2*)(bias + col);
            float2 v0, v1;
            v0.x = d[mt][nt][0] + bb.x;
            v0.y = d[mt][nt][1] + bb.y;
            v1.x = d[mt][nt][2] + bb.x;
            v1.y = d[mt][nt][3] + bb.y;
            if (doRelu) {
                v0.x = fmaxf(v0.x, 0.f); v0.y = fmaxf(v0.y, 0.f);
                v1.x = fmaxf(v1.x, 0.f); v1.y = fmaxf(v1.y, 0.f);
            }
            *(float2*)(C + (size_t)row * ldc + col) = v0;
            *(float2*)(C + (size_t)(row + 8) * ldc + col) = v1;
        }
    }
}

// ---------------- head: out[i] = t[i,:] . w[1,128] + b ----------------
__global__ void k_head(const float* __restrict__ t, const float* __restrict__ w,
                       const float* __restrict__ b, float* __restrict__ out) {
    const int gw = (blockIdx.x * blockDim.x + threadIdx.x) >> 5;
    const int lane = threadIdx.x & 31;
    if (gw >= N_NODES) return;
    float4 tv = *(const float4*)(t + (size_t)gw * HID + (lane << 2));
    float4 wv = *(const float4*)(w + (lane << 2));
    float s = tv.x * wv.x + tv.y * wv.y + tv.z * wv.z + tv.w * wv.w;
#pragma unroll
    for (int off = 16; off; off >>= 1) s += __shfl_xor_sync(0xffffffffu, s, off);
    if (lane == 0) out[gw] = s + b[0];
}

// ---------------- launch ----------------
extern "C" void kernel_launch(void* const* d_in, const int* in_sizes, int n_in,
                              void* d_out, int out_size) {
    const float* x     = (const float*)d_in[0];
    const int*   ei    = (const int*)d_in[1];
    const float* c0_w1 = (const float*)d_in[2];
    const float* c0_b1 = (const float*)d_in[3];
    const float* c0_w2 = (const float*)d_in[4];
    const float* c0_b2 = (const float*)d_in[5];
    const float* c0_w3 = (const float*)d_in[6];
    const float* c0_b3 = (const float*)d_in[7];
    const float* c1_w1 = (const float*)d_in[8];
    const float* c1_b1 = (const float*)d_in[9];
    const float* c1_w2 = (const float*)d_in[10];
    const float* c1_b2 = (const float*)d_in[11];
    const float* c1_w3 = (const float*)d_in[12];
    const float* c1_b3 = (const float*)d_in[13];
    const float* f_w1  = (const float*)d_in[14];
    const float* f_b1  = (const float*)d_in[15];
    const float* f_w2  = (const float*)d_in[16];
    const float* f_b2  = (const float*)d_in[17];
    float* out = (float*)d_out;

    const int* src = ei;
    const int* dst = ei + N_EDGES;

    float *bufA, *bufAgg, *bufH, *bufCat;
    int* cntp;
    cudaGetSymbolAddress((void**)&bufA,   g_bufA);
    cudaGetSymbolAddress((void**)&bufAgg, g_bufAgg);
    cudaGetSymbolAddress((void**)&bufH,   g_bufH);
    cudaGetSymbolAddress((void**)&bufCat, g_bufCat);
    cudaGetSymbolAddress((void**)&cntp,   g_cnt);

    const int TB = 256;
    const dim3 gEdges((N_EDGES + TB - 1) / TB);
    const dim3 gWarpPerNode((N_NODES * 32 + TB - 1) / TB);  // 5000
    const dim3 gGemm(N_NODES / 64);                          // 625, exact
    const dim3 gLinIn((N_NODES + 127) / 128);

    // CSR build (by dst)
    cudaMemsetAsync(cntp, 0, N_NODES * sizeof(int), 0);
    k_hist<<<gEdges, TB>>>(dst);
    k_scan<<<1, 1024>>>();
    k_fill<<<gEdges, TB>>>(src, dst);

    // conv0
    k_lin_in<<<gLinIn, 128>>>(x, c0_w1, c0_b1, bufA);
    k_spmm<<<gWarpPerNode, TB>>>(bufA, HID, bufAgg);
    k_gemm_mma<<<gGemm, TB>>>(bufAgg, HID, c0_w2, c0_b2, bufCat, 2 * HID, HID, 1);
    k_spmm<<<gWarpPerNode, TB>>>(bufCat, 2 * HID, bufAgg);
    k_gemm_mma<<<gGemm, TB>>>(bufAgg, HID, c0_w2, c0_b2, bufCat + HID, 2 * HID, HID, 1);
    k_gemm_mma<<<gGemm, TB>>>(bufCat, 2 * HID, c0_w3, c0_b3, bufH, HID, 2 * HID, 0);

    // conv1
    k_gemm_mma<<<gGemm, TB>>>(bufH, HID, c1_w1, c1_b1, bufA, HID, HID, 1);
    k_spmm<<<gWarpPerNode, TB>>>(bufA, HID, bufAgg);
    k_gemm_mma<<<gGemm, TB>>>(bufAgg, HID, c1_w2, c1_b2, bufCat, 2 * HID, HID, 1);
    k_spmm<<<gWarpPerNode, TB>>>(bufCat, 2 * HID, bufAgg);
    k_gemm_mma<<<gGemm, TB>>>(bufAgg, HID, c1_w2, c1_b2, bufCat + HID, 2 * HID, HID, 1);
    k_gemm_mma<<<gGemm, TB>>>(bufCat, 2 * HID, c1_w3, c1_b3, bufH, HID, 2 * HID, 0);

    // head
    k_gemm_mma<<<gGemm, TB>>>(bufH, HID, f_w1, f_b1, bufA, HID, HID, 1);
    k_head<<<gWarpPerNode, TB>>>(bufA, f_w2, f_b2, out);
}

// round 5
// speedup vs baseline: 1.7016x; 1.0443x over previous
#include <cuda_runtime.h>
#include <cuda_bf16.h>
#include <cstdint>

#define N_NODES 40000
#define N_EDGES 640000
#define HID 128

// ---------------- scratch (static __device__, no allocations) ----------------
__device__ float g_bufA  [N_NODES * HID];
__device__ float g_bufAgg[N_NODES * HID];
__device__ float g_bufH  [N_NODES * HID];
__device__ float g_bufCat[N_NODES * 2 * HID];
__device__ int   g_cnt   [N_NODES];
__device__ int   g_rp    [N_NODES + 1];
__device__ int   g_cursor[N_NODES];
__device__ int   g_csrc  [N_EDGES];
// pre-split weights (bf16 hi/lo), layout = concatenated row-major matrices
#define WOFF_C0W2 0
#define WOFF_C0W3 16384
#define WOFF_C1W1 49152
#define WOFF_C1W2 65536
#define WOFF_C1W3 81920
#define WOFF_FW1  114688
#define WTOTAL    131072
__device__ __nv_bfloat16 g_whi[WTOTAL];
__device__ __nv_bfloat16 g_wlo[WTOTAL];

// ---------------- fused: lin_in (blocks 0..2499) + hist (blocks 2500..4999) ---
__global__ __launch_bounds__(256)
void k_lin_hist(const float* __restrict__ x, const float* __restrict__ w1,
                const float* __restrict__ b1, float* __restrict__ out,
                const int* __restrict__ dst) {
    if (blockIdx.x < 2500) {
        __shared__ float xs[16 * 11];
        const int tid = threadIdx.x;
        const int col = tid & 127, half = tid >> 7;
        float wr[11];
#pragma unroll
        for (int k = 0; k < 11; k++) wr[k] = w1[col * 11 + k];
        const float bb = b1[col];
        const int row0 = blockIdx.x * 16;  // 40000/16 = 2500 exact
        for (int i = tid; i < 16 * 11; i += 256) xs[i] = x[row0 * 11 + i];
        __syncthreads();
#pragma unroll
        for (int rr = 0; rr < 8; rr++) {
            const int r = half * 8 + rr;
            float acc = bb;
#pragma unroll
            for (int k = 0; k < 11; k++) acc += xs[r * 11 + k] * wr[k];
            out[(size_t)(row0 + r) * HID + col] = fmaxf(acc, 0.f);
        }
    } else {
        int e = (blockIdx.x - 2500) * 256 + threadIdx.x;
        if (e < N_EDGES) atomicAdd(&g_cnt[dst[e]], 1);
    }
}

// ---------------- scan ----------------
__global__ void k_scan() {
    __shared__ int warpsum[32];
    __shared__ int sh_carry;
    const int tid = threadIdx.x;
    const int lane = tid & 31, wid = tid >> 5;
    if (tid == 0) sh_carry = 0;
    __syncthreads();
    for (int base = 0; base < N_NODES; base += 1024) {
        int i = base + tid;
        int v = (i < N_NODES) ? g_cnt[i] : 0;
        int s = v;
#pragma unroll
        for (int o = 1; o < 32; o <<= 1) {
            int t = __shfl_up_sync(0xffffffffu, s, o);
            if (lane >= o) s += t;
        }
        if (lane == 31) warpsum[wid] = s;
        __syncthreads();
        if (wid == 0) {
            int w = warpsum[lane];
#pragma unroll
            for (int o = 1; o < 32; o <<= 1) {
                int t = __shfl_up_sync(0xffffffffu, w, o);
                if (lane >= o) w += t;
            }
            warpsum[lane] = w;
        }
        __syncthreads();
        int incl = s + (wid ? warpsum[wid - 1] : 0) + sh_carry;
        int excl = incl - v;
        if (i < N_NODES) { g_rp[i] = excl; g_cursor[i] = excl; }
        __syncthreads();
        if (tid == 1023) sh_carry = incl;
        __syncthreads();
    }
    if (tid == 0) g_rp[N_NODES] = sh_carry;
}

__global__ void k_fill(const int* __restrict__ src, const int* __restrict__ dst) {
    int e = blockIdx.x * blockDim.x + threadIdx.x;
    if (e < N_EDGES) {
        int p = atomicAdd(&g_cursor[dst[e]], 1);
        g_csrc[p] = src[e];
    }
}

// ---------------- SpMM: agg[d] = sum over edges (dst=d) of h[src] ----------------
__global__ void k_spmm(const float* __restrict__ h, int lda, float* __restrict__ agg) {
    const int gw = (blockIdx.x * blockDim.x + threadIdx.x) >> 5;
    const int lane = threadIdx.x & 31;
    if (gw >= N_NODES) return;
    const int beg = g_rp[gw], end = g_rp[gw + 1];
    const int off = lane << 2;
    float4 acc = make_float4(0.f, 0.f, 0.f, 0.f);
    int e = beg;
    for (; e + 3 < end; e += 4) {
        int s0 = g_csrc[e], s1 = g_csrc[e + 1], s2 = g_csrc[e + 2], s3 = g_csrc[e + 3];
        float4 v0 = *(const float4*)(h + (size_t)s0 * lda + off);
        float4 v1 = *(const float4*)(h + (size_t)s1 * lda + off);
        float4 v2 = *(const float4*)(h + (size_t)s2 * lda + off);
        float4 v3 = *(const float4*)(h + (size_t)s3 * lda + off);
        acc.x += (v0.x + v1.x) + (v2.x + v3.x);
        acc.y += (v0.y + v1.y) + (v2.y + v3.y);
        acc.z += (v0.z + v1.z) + (v2.z + v3.z);
        acc.w += (v0.w + v1.w) + (v2.w + v3.w);
    }
    for (; e < end; e++) {
        int s0 = g_csrc[e];
        float4 v0 = *(const float4*)(h + (size_t)s0 * lda + off);
        acc.x += v0.x; acc.y += v0.y; acc.z += v0.z; acc.w += v0.w;
    }
    *(float4*)(agg + (size_t)gw * HID + off) = acc;
}

// ---------------- weight pre-split: fp32 -> bf16 hi + bf16 lo ----------------
__global__ void k_wsplit(const float* __restrict__ s0, const float* __restrict__ s1,
                         const float* __restrict__ s2, const float* __restrict__ s3,
                         const float* __restrict__ s4, const float* __restrict__ s5) {
    int i = blockIdx.x * 256 + threadIdx.x;
    if (i >= WTOTAL) return;
    const float* src;
    int local;
    if (i < WOFF_C0W3)      { src = s0; local = i; }
    else if (i < WOFF_C1W1) { src = s1; local = i - WOFF_C0W3; }
    else if (i < WOFF_C1W2) { src = s2; local = i - WOFF_C1W1; }
    else if (i < WOFF_C1W3) { src = s3; local = i - WOFF_C1W2; }
    else if (i < WOFF_FW1)  { src = s4; local = i - WOFF_C1W3; }
    else                    { src = s5; local = i - WOFF_FW1; }
    float v = src[local];
    __nv_bfloat16 h = __float2bfloat16_rn(v);
    g_whi[i] = h;
    g_wlo[i] = __float2bfloat16_rn(v - __bfloat162float(h));
}

// ================= mma.sync bf16x3 GEMM =================
// Block 64x128, 8 warps (2x4), warp tile 32x32, k-step 16.
// A split to bf16 hi/lo in loader; W pre-split in gmem.

__device__ __forceinline__ uint32_t smem_u32(const void* p) {
    uint32_t a;
    asm("{ .reg .u64 t; cvta.to.shared.u64 t, %1; cvt.u32.u64 %0, t; }"
        : "=r"(a) : "l"(p));
    return a;
}

__device__ __forceinline__ void mma_bf16(float d[4], const uint32_t a[4],
                                         const uint32_t b[2]) {
    asm volatile(
        "mma.sync.aligned.m16n8k16.row.col.f32.bf16.bf16.f32 "
        "{%0,%1,%2,%3}, {%4,%5,%6,%7}, {%8,%9}, {%0,%1,%2,%3};"
        : "+f"(d[0]), "+f"(d[1]), "+f"(d[2]), "+f"(d[3])
        : "r"(a[0]), "r"(a[1]), "r"(a[2]), "r"(a[3]), "r"(b[0]), "r"(b[1]));
}

#define LDMX4(r, addr) \
    asm volatile("ldmatrix.sync.aligned.m8n8.x4.shared.b16 {%0,%1,%2,%3}, [%4];" \
                 : "=r"((r)[0]), "=r"((r)[1]), "=r"((r)[2]), "=r"((r)[3]) : "r"(addr))
#define LDMX2(r, addr) \
    asm volatile("ldmatrix.sync.aligned.m8n8.x2.shared.b16 {%0,%1}, [%2];" \
                 : "=r"((r)[0]), "=r"((r)[1]) : "r"(addr))

__device__ __forceinline__ uint32_t pack_hi(float x, float y, float& lx, float& ly) {
    __nv_bfloat162 h = __floats2bfloat162_rn(x, y);
    lx = x - __bfloat162float(h.x);
    ly = y - __bfloat162float(h.y);
    return *(uint32_t*)&h;
}
__device__ __forceinline__ uint32_t pack_bf2(float x, float y) {
    __nv_bfloat162 h = __floats2bfloat162_rn(x, y);
    return *(uint32_t*)&h;
}

// SMEM per stage: Ahi[64 x 48B]=3072, Alo 3072, Whi[128 x 48B]=6144, Wlo 6144
#define ST_AHI 0
#define ST_ALO 3072
#define ST_WHI 6144
#define ST_WLO 12288
#define ST_SZ  18432

__global__ __launch_bounds__(256, 2)
void k_gemm_mma(const float* __restrict__ A, int lda,
                const __nv_bfloat16* __restrict__ Whi,  // [128, K] bf16
                const __nv_bfloat16* __restrict__ Wlo,
                const float* __restrict__ bias,
                float* __restrict__ C, int ldc, int K, int doRelu) {
    __shared__ __align__(16) char sm[2][ST_SZ];

    const int tid = threadIdx.x, warp = tid >> 5, lane = tid & 31;
    const int wr = warp >> 2, wc = warp & 3;
    const int row0 = blockIdx.x * 64;

    const int ar = tid >> 2, aq = tid & 3;  // A: 64 rows x 4 float4
    const int wn = tid >> 1, wh = tid & 1;  // W: 128 rows x 2 halves (8 bf16)

    const float* aptr = A + (size_t)(row0 + ar) * lda + 4 * aq;
    const __nv_bfloat16* whptr = Whi + (size_t)wn * K + 8 * wh;
    const __nv_bfloat16* wlptr = Wlo + (size_t)wn * K + 8 * wh;

    const uint32_t sA0 = smem_u32(&sm[0][0]);
    const uint32_t sA1 = smem_u32(&sm[1][0]);

    const uint32_t a_lo = (uint32_t)(((wr * 32) + (lane & 7) + ((lane >> 3) & 1) * 8) * 48
                                     + ((lane >> 4) * 16));
    const uint32_t b_lo = (uint32_t)(((wc * 32) + (lane & 7)) * 48 + ((lane >> 3) & 1) * 16);

    const uint32_t a_st = (uint32_t)(ar * 48 + 8 * aq);
    const uint32_t w_st = (uint32_t)(wn * 48 + 16 * wh);

    float d[2][4][4];
#pragma unroll
    for (int mt = 0; mt < 2; mt++)
#pragma unroll
        for (int nt = 0; nt < 4; nt++)
#pragma unroll
            for (int i = 0; i < 4; i++) d[mt][nt][i] = 0.f;

    const int nst = K >> 4;
    float4 a4;
    uint4 wh4, wl4;

    a4 = *(const float4*)aptr;
    wh4 = *(const uint4*)whptr;
    wl4 = *(const uint4*)wlptr;

    {
        char* st = sm[0];
        float lx, ly;
        uint32_t h01 = pack_hi(a4.x, a4.y, lx, ly);
        uint32_t l01 = pack_bf2(lx, ly);
        uint32_t h23 = pack_hi(a4.z, a4.w, lx, ly);
        uint32_t l23 = pack_bf2(lx, ly);
        *(uint32_t*)(st + ST_AHI + a_st) = h01;
        *(uint32_t*)(st + ST_AHI + a_st + 4) = h23;
        *(uint32_t*)(st + ST_ALO + a_st) = l01;
        *(uint32_t*)(st + ST_ALO + a_st + 4) = l23;
        *(uint4*)(st + ST_WHI + w_st) = wh4;
        *(uint4*)(st + ST_WLO + w_st) = wl4;
    }
    __syncthreads();

    for (int s = 0; s < nst; s++) {
        if (s + 1 < nst) {
            a4 = *(const float4*)(aptr + (s + 1) * 16);
            wh4 = *(const uint4*)(whptr + (s + 1) * 16);
            wl4 = *(const uint4*)(wlptr + (s + 1) * 16);
        }
        const uint32_t sb = (s & 1) ? sA1 : sA0;

        uint32_t ah[2][4], al[2][4], bh[4][2], bl[4][2];
#pragma unroll
        for (int mt = 0; mt < 2; mt++) {
            LDMX4(ah[mt], sb + ST_AHI + a_lo + mt * 16 * 48);
            LDMX4(al[mt], sb + ST_ALO + a_lo + mt * 16 * 48);
        }
#pragma unroll
        for (int nt = 0; nt < 4; nt++) {
            LDMX2(bh[nt], sb + ST_WHI + b_lo + nt * 8 * 48);
            LDMX2(bl[nt], sb + ST_WLO + b_lo + nt * 8 * 48);
        }
#pragma unroll
        for (int mt = 0; mt < 2; mt++)
#pragma unroll
            for (int nt = 0; nt < 4; nt++) {
                mma_bf16(d[mt][nt], al[mt], bh[nt]);
                mma_bf16(d[mt][nt], ah[mt], bl[nt]);
                mma_bf16(d[mt][nt], ah[mt], bh[nt]);
            }

        if (s + 1 < nst) {
            char* st = sm[(s + 1) & 1];
            float lx, ly;
            uint32_t h01 = pack_hi(a4.x, a4.y, lx, ly);
            uint32_t l01 = pack_bf2(lx, ly);
            uint32_t h23 = pack_hi(a4.z, a4.w, lx, ly);
            uint32_t l23 = pack_bf2(lx, ly);
            *(uint32_t*)(st + ST_AHI + a_st) = h01;
            *(uint32_t*)(st + ST_AHI + a_st + 4) = h23;
            *(uint32_t*)(st + ST_ALO + a_st) = l01;
            *(uint32_t*)(st + ST_ALO + a_st + 4) = l23;
            *(uint4*)(st + ST_WHI + w_st) = wh4;
            *(uint4*)(st + ST_WLO + w_st) = wl4;
            __syncthreads();
        }
    }

#pragma unroll
    for (int mt = 0; mt < 2; mt++) {
        const int row = row0 + wr * 32 + mt * 16 + (lane >> 2);
#pragma unroll
        for (int nt = 0; nt < 4; nt++) {
            const int col = wc * 32 + nt * 8 + 2 * (lane & 3);
            float2 bb = *(const float2*)(bias + col);
            float2 v0, v1;
            v0.x = d[mt][nt][0] + bb.x;
            v0.y = d[mt][nt][1] + bb.y;
            v1.x = d[mt][nt][2] + bb.x;
            v1.y = d[mt][nt][3] + bb.y;
            if (doRelu) {
                v0.x = fmaxf(v0.x, 0.f); v0.y = fmaxf(v0.y, 0.f);
                v1.x = fmaxf(v1.x, 0.f); v1.y = fmaxf(v1.y, 0.f);
            }
            *(float2*)(C + (size_t)row * ldc + col) = v0;
            *(float2*)(C + (size_t)(row + 8) * ldc + col) = v1;
        }
    }
}

// ---------------- head ----------------
__global__ void k_head(const float* __restrict__ t, const float* __restrict__ w,
                       const float* __restrict__ b, float* __restrict__ out) {
    const int gw = (blockIdx.x * blockDim.x + threadIdx.x) >> 5;
    const int lane = threadIdx.x & 31;
    if (gw >= N_NODES) return;
    float4 tv = *(const float4*)(t + (size_t)gw * HID + (lane << 2));
    float4 wv = *(const float4*)(w + (lane << 2));
    float s = tv.x * wv.x + tv.y * wv.y + tv.z * wv.z + tv.w * wv.w;
#pragma unroll
    for (int off = 16; off; off >>= 1) s += __shfl_xor_sync(0xffffffffu, s, off);
    if (lane == 0) out[gw] = s + b[0];
}

// ---------------- launch ----------------
extern "C" void kernel_launch(void* const* d_in, const int* in_sizes, int n_in,
                              void* d_out, int out_size) {
    const float* x     = (const float*)d_in[0];
    const int*   ei    = (const int*)d_in[1];
    const float* c0_w1 = (const float*)d_in[2];
    const float* c0_b1 = (const float*)d_in[3];
    const float* c0_w2 = (const float*)d_in[4];
    const float* c0_b2 = (const float*)d_in[5];
    const float* c0_w3 = (const float*)d_in[6];
    const float* c0_b3 = (const float*)d_in[7];
    const float* c1_w1 = (const float*)d_in[8];
    const float* c1_b1 = (const float*)d_in[9];
    const float* c1_w2 = (const float*)d_in[10];
    const float* c1_b2 = (const float*)d_in[11];
    const float* c1_w3 = (const float*)d_in[12];
    const float* c1_b3 = (const float*)d_in[13];
    const float* f_w1  = (const float*)d_in[14];
    const float* f_b1  = (const float*)d_in[15];
    const float* f_w2  = (const float*)d_in[16];
    const float* f_b2  = (const float*)d_in[17];
    float* out = (float*)d_out;

    const int* src = ei;
    const int* dst = ei + N_EDGES;

    float *bufA, *bufAgg, *bufH, *bufCat;
    int* cntp;
    __nv_bfloat16 *whi, *wlo;
    cudaGetSymbolAddress((void**)&bufA,   g_bufA);
    cudaGetSymbolAddress((void**)&bufAgg, g_bufAgg);
    cudaGetSymbolAddress((void**)&bufH,   g_bufH);
    cudaGetSymbolAddress((void**)&bufCat, g_bufCat);
    cudaGetSymbolAddress((void**)&cntp,   g_cnt);
    cudaGetSymbolAddress((void**)&whi,    g_whi);
    cudaGetSymbolAddress((void**)&wlo,    g_wlo);

    const int TB = 256;
    const dim3 gEdges((N_EDGES + TB - 1) / TB);                // 2500
    const dim3 gWarpPerNode((N_NODES * 32 + TB - 1) / TB);     // 5000
    const dim3 gGemm(N_NODES / 64);                            // 625
    const dim3 gWsplit((WTOTAL + 255) / 256);                  // 512

    cudaMemsetAsync(cntp, 0, N_NODES * sizeof(int), 0);
    // slot 1: fused lin_in + hist
    k_lin_hist<<<5000, TB>>>(x, c0_w1, c0_b1, bufA, dst);
    // slot 2-3: scan, fill
    k_scan<<<1, 1024>>>();
    k_fill<<<gEdges, TB>>>(src, dst);
    // slot 4 (ncu-captured): first spmm
    k_spmm<<<gWarpPerNode, TB>>>(bufA, HID, bufAgg);
    // weight pre-split (before first gemm)
    k_wsplit<<<gWsplit, 256>>>(c0_w2, c0_w3, c1_w1, c1_w2, c1_w3, f_w1);

    // conv0
    k_gemm_mma<<<gGemm, TB>>>(bufAgg, HID, whi + WOFF_C0W2, wlo + WOFF_C0W2, c0_b2,
                              bufCat, 2 * HID, HID, 1);
    k_spmm<<<gWarpPerNode, TB>>>(bufCat, 2 * HID, bufAgg);
    k_gemm_mma<<<gGemm, TB>>>(bufAgg, HID, whi + WOFF_C0W2, wlo + WOFF_C0W2, c0_b2,
                              bufCat + HID, 2 * HID, HID, 1);
    k_gemm_mma<<<gGemm, TB>>>(bufCat, 2 * HID, whi + WOFF_C0W3, wlo + WOFF_C0W3, c0_b3,
                              bufH, HID, 2 * HID, 0);

    // conv1
    k_gemm_mma<<<gGemm, TB>>>(bufH, HID, whi + WOFF_C1W1, wlo + WOFF_C1W1, c1_b1,
                              bufA, HID, HID, 1);
    k_spmm<<<gWarpPerNode, TB>>>(bufA, HID, bufAgg);
    k_gemm_mma<<<gGemm, TB>>>(bufAgg, HID, whi + WOFF_C1W2, wlo + WOFF_C1W2, c1_b2,
                              bufCat, 2 * HID, HID, 1);
    k_spmm<<<gWarpPerNode, TB>>>(bufCat, 2 * HID, bufAgg);
    k_gemm_mma<<<gGemm, TB>>>(bufAgg, HID, whi + WOFF_C1W2, wlo + WOFF_C1W2, c1_b2,
                              bufCat + HID, 2 * HID, HID, 1);
    k_gemm_mma<<<gGemm, TB>>>(bufCat, 2 * HID, whi + WOFF_C1W3, wlo + WOFF_C1W3, c1_b3,
                              bufH, HID, 2 * HID, 0);

    // head
    k_gemm_mma<<<gGemm, TB>>>(bufH, HID, whi + WOFF_FW1, wlo + WOFF_FW1, f_b1,
                              bufA, HID, HID, 1);
    k_head<<<gWarpPerNode, TB>>>(bufA, f_w2, f_b2, out);
}